// round 5
// baseline (speedup 1.0000x reference)
#include <cuda_runtime.h>
#include <cstdint>
#include <cstddef>

#define NCH    64
#define OCH    64
#define CONVCH 4096
#define HH     56
#define WW     56
#define PLANE  (HH*WW)     // 3136
#define NPIX   14          // pixels per thread
#define ROWS_HALF 28
#define TROW   30          // tile rows incl. halo
#define SEGW   20          // floats per segment (16 used + 4 pad)
#define TCOL   (4*SEGW)    // 80 floats per tile row
#define NREF   128         // 16 mean-groups * 8 max-group
#define NTHR   128
#define NACT   112         // 4 threads/row * 28 rows
#define NJOB   (TROW*14)   // 420 float4 fill jobs per tile

__global__ __launch_bounds__(NTHR, 4)
void prcn_kernel(const float* __restrict__ x,
                 const float* __restrict__ Wt,      // [4096,9]
                 const float* __restrict__ bias,    // [4096]
                 const void*  __restrict__ index_raw, // int32 or int64 [8192]
                 float* __restrict__ out)           // [8,64,56,56]
{
    // Segmented tile: row = 4 segments of 20 floats. Segment t holds plane
    // cols [14t-1 .. 14t+14] at positions 0..15 (boundary cols duplicated).
    // Compute threads read their window as 4 conflict-free LDS.128.
    __shared__ float tile[2][TROW][TCOL];        // 19200 B
    __shared__ float wsm[NREF][10];              // 9 weights + bias per ref
    __shared__ int   cidx[NREF];
    __shared__ __align__(16) int coltab[56];     // col -> prim|dup packed offsets

    const int tid = threadIdx.x;
    const int o   = blockIdx.x & 63;
    const int b   = blockIdx.x >> 6;

    // --- index dtype detection: int32 (JAX x64 off) vs int64 ---
    const int* idx32 = (const int*)index_raw;
    const bool is64 = ((idx32[1] | idx32[3] | idx32[5] | idx32[7]) == 0);

    if (tid < NREF) {
        int v = is64 ? (int)((const long long*)index_raw)[o*NREF + tid]
                     : idx32[o*NREF + tid];
        cidx[tid] = v & (CONVCH - 1);
    }
    if (tid < 56) {
        int c = tid, t = c / 14, p = c - 14*t + 1;   // position in primary segment
        int prim = t*SEGW + p;
        int dup  = 0;
        if (p == 1  && t > 0) dup = (t-1)*SEGW + 15 + 1;  // col 14t also ends seg t-1
        if (p == 14 && t < 3) dup = (t+1)*SEGW + 0  + 1;  // col 14t+13 also starts seg t+1
        coltab[c] = prim | (dup << 16);
    }
    // Zero both buffers once: halo slots (seg0 pos0, seg3 pos15, pads 16..19)
    // are never written by fills and must stay zero forever.
    for (int j = tid; j < 2*TROW*TCOL; j += NTHR) ((float*)tile)[j] = 0.f;
    __syncthreads();
    for (int j = tid; j < NREF*10; j += NTHR) {
        int k = j / 10, l = j - k*10;
        int c = cidx[k];
        wsm[k][l] = (l < 9) ? Wt[c*9 + l] : bias[c];
    }
    __syncthreads();

    const int tr = tid >> 2;        // row in half (0..27) for tid < NACT
    const int tx = tid & 3;         // segment index

    // Per-thread fill-job geometry (static across channels)
    int jr[4], jc[4];
    #pragma unroll
    for (int m = 0; m < 4; m++) {
        int j = tid + m*NTHR;
        jr[m] = j / 14;
        jc[m] = (j - jr[m]*14) * 4;
    }

    for (int half = 0; half < 2; half++) {
        const int r0 = half * ROWS_HALF;

        float4 R[4];
        // Prologue: fetch channel 0 tile into registers
        {
            const int ic = cidx[0] >> 6;
            const float* xp = x + (size_t)(b*NCH + ic) * PLANE;
            #pragma unroll
            for (int m = 0; m < 4; m++) {
                R[m] = make_float4(0.f, 0.f, 0.f, 0.f);
                if (tid + m*NTHR < NJOB) {
                    int pr = r0 - 1 + jr[m];
                    if (pr >= 0 && pr < HH)
                        R[m] = *(const float4*)(xp + pr*WW + jc[m]);
                }
            }
        }

        float acc[NPIX], mx[NPIX];
        #pragma unroll
        for (int p = 0; p < NPIX; p++) acc[p] = 0.f;

        for (int k = 0; k < NREF; k++) {
            // Scatter prefetched registers into segmented tile[k&1]
            float* Tb = &tile[k & 1][0][0];
            #pragma unroll
            for (int m = 0; m < 4; m++) {
                if (tid + m*NTHR < NJOB) {
                    float* rowp = Tb + jr[m]*TCOL;
                    int4 e = *(const int4*)&coltab[jc[m]];
                    float vx = R[m].x, vy = R[m].y, vz = R[m].z, vw = R[m].w;
                    rowp[e.x & 0xFFFF] = vx; if (e.x >> 16) rowp[(e.x >> 16) - 1] = vx;
                    rowp[e.y & 0xFFFF] = vy; if (e.y >> 16) rowp[(e.y >> 16) - 1] = vy;
                    rowp[e.z & 0xFFFF] = vz; if (e.z >> 16) rowp[(e.z >> 16) - 1] = vz;
                    rowp[e.w & 0xFFFF] = vw; if (e.w >> 16) rowp[(e.w >> 16) - 1] = vw;
                }
            }
            __syncthreads();   // tile[k&1] ready; everyone left tile[(k-1)&1]

            // Prefetch channel k+1 (LDG latency hides under compute below)
            if (k + 1 < NREF) {
                const int ic = cidx[k+1] >> 6;
                const float* xp = x + (size_t)(b*NCH + ic) * PLANE;
                #pragma unroll
                for (int m = 0; m < 4; m++) {
                    R[m] = make_float4(0.f, 0.f, 0.f, 0.f);
                    if (tid + m*NTHR < NJOB) {
                        int pr = r0 - 1 + jr[m];
                        if (pr >= 0 && pr < HH)
                            R[m] = *(const float4*)(xp + pr*WW + jc[m]);
                    }
                }
            }

            if (tid < NACT) {
                float wv[10];
                #pragma unroll
                for (int l = 0; l < 10; l++) wv[l] = wsm[k][l];

                float s[NPIX];
                #pragma unroll
                for (int p = 0; p < NPIX; p++) s[p] = wv[9];   // bias

                #pragma unroll
                for (int ky = 0; ky < 3; ky++) {
                    const float* segp = &tile[k & 1][tr + ky][tx*SEGW];
                    float4 q0 = *(const float4*)(segp +  0);
                    float4 q1 = *(const float4*)(segp +  4);
                    float4 q2 = *(const float4*)(segp +  8);
                    float4 q3 = *(const float4*)(segp + 12);
                    float v[16] = {q0.x,q0.y,q0.z,q0.w, q1.x,q1.y,q1.z,q1.w,
                                   q2.x,q2.y,q2.z,q2.w, q3.x,q3.y,q3.z,q3.w};
                    #pragma unroll
                    for (int p = 0; p < NPIX; p++)
                        s[p] += wv[3*ky]*v[p] + wv[3*ky+1]*v[p+1] + wv[3*ky+2]*v[p+2];
                }

                if ((k & 7) == 0) {
                    #pragma unroll
                    for (int p = 0; p < NPIX; p++) mx[p] = s[p];
                } else {
                    #pragma unroll
                    for (int p = 0; p < NPIX; p++) mx[p] = fmaxf(mx[p], s[p]);
                }
                if ((k & 7) == 7) {
                    #pragma unroll
                    for (int p = 0; p < NPIX; p++) acc[p] += mx[p];
                }
            }
        }

        if (tid < NACT) {
            const int h = r0 + tr;
            float* op = out + ((size_t)(b*OCH + o)*HH + h)*WW + tx*NPIX;
            #pragma unroll
            for (int p = 0; p < NPIX; p++) op[p] = acc[p] * 0.0625f;
        }
    }
}

extern "C" void kernel_launch(void* const* d_in, const int* in_sizes, int n_in,
                              void* d_out, int out_size) {
    const float* x    = (const float*)d_in[0];
    const float* Wt   = (const float*)d_in[1];
    const float* bias = (const float*)d_in[2];
    const void*  idx  = (const void*)d_in[3];
    float* out = (float*)d_out;
    prcn_kernel<<<OCH * 8, NTHR>>>(x, Wt, bias, idx, out);
}

// round 7
// speedup vs baseline: 1.8135x; 1.8135x over previous
#include <cuda_runtime.h>
#include <cstdint>
#include <cstddef>

#define NCH    64
#define OCH    64
#define CONVCH 4096
#define HH     56
#define WW     56
#define PLANE  (HH*WW)     // 3136
#define NPIX   14          // pixels per thread (per output row)
#define TROW   58          // full plane + 2 halo rows
#define TCOL   68          // row stride: 2*68=136 ≡ 8 (mod 32) -> 2-way conflicts;
                           // 68*4 ≡ 0 (mod 16) -> every row 16B aligned for cp.async
#define NREF   128
#define NTHR   128
#define NACT   112         // 28 row-pairs * 4 col strips
#define NJOB   (HH*14)     // 784 float4 fill jobs (all rows valid, no predication)

__device__ __forceinline__ void cp_async16(void* dst, const void* src) {
    unsigned d = (unsigned)__cvta_generic_to_shared(dst);
    asm volatile("cp.async.cg.shared.global [%0], [%1], 16;\n" :: "r"(d), "l"(src));
}
__device__ __forceinline__ void cp_commit() { asm volatile("cp.async.commit_group;\n" ::: "memory"); }
__device__ __forceinline__ void cp_wait0()  { asm volatile("cp.async.wait_group 0;\n" ::: "memory"); }

__global__ __launch_bounds__(NTHR, 4)
void prcn_kernel(const float* __restrict__ x,
                 const float* __restrict__ Wt,      // [4096,9]
                 const float* __restrict__ bias,    // [4096]
                 const void*  __restrict__ index_raw, // int32 or int64 [8192]
                 float* __restrict__ out)           // [8,64,56,56]
{
    __shared__ float tile[2][TROW][TCOL];   // 31552 B double buffer
    __shared__ float wsm[NREF][10];
    __shared__ int   cidx[NREF];

    const int tid = threadIdx.x;
    const int o   = blockIdx.x & 63;
    const int b   = blockIdx.x >> 6;

    // --- index dtype detection: int32 (JAX x64 off) vs int64 ---
    const int* idx32 = (const int*)index_raw;
    const bool is64 = ((idx32[1] | idx32[3] | idx32[5] | idx32[7]) == 0);

    if (tid < NREF) {
        int v = is64 ? (int)((const long long*)index_raw)[o*NREF + tid]
                     : idx32[o*NREF + tid];
        cidx[tid] = v & (CONVCH - 1);
    }
    // Zero both buffers once. Fills rewrite rows 1..56, cols [4,59] every
    // channel; halo rows 0,57 and cols 0..3 / 60..67 stay zero forever.
    for (int j = tid; j < 2*TROW*TCOL; j += NTHR) ((float*)tile)[j] = 0.f;
    __syncthreads();
    for (int j = tid; j < NREF*10; j += NTHR) {
        int k = j / 10, l = j - k*10;
        int c = cidx[k];
        wsm[k][l] = (l < 9) ? Wt[c*9 + l] : bias[c];
    }
    __syncthreads();

    // Fill-job geometry: job j -> plane row rr=j/14, col cc=(j%14)*4.
    // dst = tile[buf][rr+1][cc+4], src = x-plane + rr*56 + cc. 7 jobs/thread max.
    int doff[7], soff[7];
    #pragma unroll
    for (int m = 0; m < 7; m++) {
        int j = tid + m*NTHR;
        int rr = j / 14, cc = (j - rr*14) * 4;
        doff[m] = (rr + 1)*TCOL + cc + 4;   // floats, relative to buffer base
        soff[m] = rr*WW + cc;
    }
    const bool job6 = (tid + 6*NTHR) < NJOB;   // only tid<16 has a 7th job

    const int tr = tid >> 2;        // row-pair index 0..27 (tid < NACT)
    const int tx = tid & 3;
    const int basec = tx*NPIX + 3;

    // Prologue: fill(0)
    {
        const float* xp = x + (size_t)(b*NCH + (cidx[0] >> 6)) * PLANE;
        float* Tb = &tile[0][0][0];
        #pragma unroll
        for (int m = 0; m < 6; m++) cp_async16(Tb + doff[m], xp + soff[m]);
        if (job6) cp_async16(Tb + doff[6], xp + soff[6]);
        cp_commit();
    }

    float acc0[NPIX], acc1[NPIX], mx0[NPIX], mx1[NPIX];
    #pragma unroll
    for (int p = 0; p < NPIX; p++) { acc0[p] = 0.f; acc1[p] = 0.f; }

    for (int k = 0; k < NREF; k++) {
        cp_wait0();          // fill(k) landed (this thread's part)
        __syncthreads();     // landed everywhere; compute(k-1) done everywhere

        if (k + 1 < NREF) {  // fill(k+1) overlaps compute(k)
            const float* xp = x + (size_t)(b*NCH + (cidx[k+1] >> 6)) * PLANE;
            float* Tb = &tile[(k+1) & 1][0][0];
            #pragma unroll
            for (int m = 0; m < 6; m++) cp_async16(Tb + doff[m], xp + soff[m]);
            if (job6) cp_async16(Tb + doff[6], xp + soff[6]);
            cp_commit();
        }

        if (tid < NACT) {
            float wv[10];
            #pragma unroll
            for (int l = 0; l < 10; l++) wv[l] = wsm[k][l];

            float s0[NPIX], s1[NPIX];
            #pragma unroll
            for (int p = 0; p < NPIX; p++) { s0[p] = wv[9]; s1[p] = wv[9]; }

            // 4-row window: tile rows 2tr .. 2tr+3 cover plane rows 2tr-1 .. 2tr+2.
            // Output row A (plane 2tr)  uses window rows 0,1,2 with w-rows 0,1,2.
            // Output row B (plane 2tr+1) uses window rows 1,2,3 with w-rows 0,1,2.
            #pragma unroll
            for (int ky = 0; ky < 4; ky++) {
                const float* rp = &tile[k & 1][2*tr + ky][basec];
                float v[NPIX + 2];
                #pragma unroll
                for (int i = 0; i < NPIX + 2; i++) v[i] = rp[i];
                if (ky < 3) {
                    const float w0 = wv[3*ky], w1 = wv[3*ky+1], w2 = wv[3*ky+2];
                    #pragma unroll
                    for (int p = 0; p < NPIX; p++)
                        s0[p] += w0*v[p] + w1*v[p+1] + w2*v[p+2];
                }
                if (ky > 0) {
                    const float w0 = wv[3*(ky-1)], w1 = wv[3*(ky-1)+1], w2 = wv[3*(ky-1)+2];
                    #pragma unroll
                    for (int p = 0; p < NPIX; p++)
                        s1[p] += w0*v[p] + w1*v[p+1] + w2*v[p+2];
                }
            }

            if ((k & 7) == 0) {
                #pragma unroll
                for (int p = 0; p < NPIX; p++) { mx0[p] = s0[p]; mx1[p] = s1[p]; }
            } else {
                #pragma unroll
                for (int p = 0; p < NPIX; p++) {
                    mx0[p] = fmaxf(mx0[p], s0[p]);
                    mx1[p] = fmaxf(mx1[p], s1[p]);
                }
            }
            if ((k & 7) == 7) {
                #pragma unroll
                for (int p = 0; p < NPIX; p++) { acc0[p] += mx0[p]; acc1[p] += mx1[p]; }
            }
        }
    }

    if (tid < NACT) {
        float* op = out + ((size_t)(b*OCH + o)*HH + 2*tr)*WW + tx*NPIX;
        #pragma unroll
        for (int p = 0; p < NPIX; p++) op[p]      = acc0[p] * 0.0625f;
        #pragma unroll
        for (int p = 0; p < NPIX; p++) op[WW + p] = acc1[p] * 0.0625f;
    }
}

extern "C" void kernel_launch(void* const* d_in, const int* in_sizes, int n_in,
                              void* d_out, int out_size) {
    const float* x    = (const float*)d_in[0];
    const float* Wt   = (const float*)d_in[1];
    const float* bias = (const float*)d_in[2];
    const void*  idx  = (const void*)d_in[3];
    float* out = (float*)d_out;
    prcn_kernel<<<OCH * 8, NTHR>>>(x, Wt, bias, idx, out);
}